// round 1
// baseline (speedup 1.0000x reference)
#include <cuda_runtime.h>
#include <math.h>

#define B_  16
#define C_  256
#define H_  64
#define W_  64
#define K_  7
#define PAD 3
#define HW  (H_ * W_)          // 4096
#define KK  (K_ * K_)          // 49
#define CR  (C_ / 4)           // 64 hidden dim
#define CKK (C_ * KK)          // 12544

// ---------------- scratch (device globals; no allocs allowed) ----------------
__device__ float g_pooled[B_ * C_];          // [B, C] mean
__device__ float g_h[B_ * CR];               // [B, 64] gelu hidden
__device__ float g_fused[B_ * C_ * KK];      // [B, C, 49] fused dyn kernels
__device__ float g_tmp[B_ * C_ * HW];        // [B, C, H, W] depthwise output (67 MB)

// ---------------- 1) global average pool: x -> pooled[b,c] ----------------
__global__ void pool_kernel(const float* __restrict__ x) {
    // one block per (b,c) plane; 256 threads reduce 4096 elements
    int plane = blockIdx.x;               // b*C + c
    const float* p = x + (size_t)plane * HW;
    int tid = threadIdx.x;
    float s = 0.f;
    #pragma unroll
    for (int i = 0; i < HW / 256; i++) s += p[tid + i * 256];
    // block reduction
    __shared__ float red[256];
    red[tid] = s;
    __syncthreads();
    for (int off = 128; off >= 32; off >>= 1) {
        if (tid < off) red[tid] += red[tid + off];
        __syncthreads();
    }
    if (tid < 32) {
        float v = red[tid];
        #pragma unroll
        for (int off = 16; off > 0; off >>= 1)
            v += __shfl_down_sync(0xffffffffu, v, off);
        if (tid == 0) g_pooled[plane] = v * (1.0f / HW);
    }
}

// ---------------- 2) h = gelu(pooled @ w1.T + b1) ----------------
// w1: [64, 256] row-major. 16*64 = 1024 outputs, one block.
__global__ void mlp1_kernel(const float* __restrict__ w1, const float* __restrict__ b1) {
    int tid = threadIdx.x;                // 0..1023
    int b = tid >> 6;                     // /64
    int j = tid & 63;
    const float* pr = g_pooled + b * C_;
    const float* wr = w1 + j * C_;
    float acc = b1[j];
    #pragma unroll 8
    for (int c = 0; c < C_; c++) acc += pr[c] * wr[c];
    // exact gelu: 0.5*x*(1+erf(x/sqrt(2)))
    float g = 0.5f * acc * (1.0f + erff(acc * 0.70710678118654752f));
    g_h[tid] = g;
}

// ---------------- 3) fused[b, r] = dw[r] + b2[r] + sum_j h[b,j]*w2[r,j] ----------------
// w2: [12544, 64] row-major; r = c*49 + t
__global__ void gen_kernel(const float* __restrict__ dw, const float* __restrict__ w2,
                           const float* __restrict__ b2) {
    int idx = blockIdx.x * blockDim.x + threadIdx.x;   // 0 .. 16*12544-1
    if (idx >= B_ * CKK) return;
    int b = idx / CKK;
    int r = idx - b * CKK;
    const float* hv = g_h + b * CR;
    const float* wr = w2 + (size_t)r * CR;
    float acc = b2[r] + dw[r];
    #pragma unroll
    for (int j = 0; j < CR; j++) acc += hv[j] * wr[j];
    g_fused[idx] = acc;
}

// ---------------- 4) per-sample depthwise 7x7 conv -> g_tmp ----------------
// grid: (HW/256 = 16 row-tiles, C, B); block 256 threads = 4 rows x 64 cols
__global__ void dwconv_kernel(const float* __restrict__ x) {
    __shared__ float wsm[KK];
    __shared__ float tile[10][70];        // 4+6 rows, 64+6 cols halo

    int b = blockIdx.z, c = blockIdx.y;
    int y0 = blockIdx.x * 4;              // first output row of this tile
    int tid = threadIdx.x;

    const float* plane = x + ((size_t)(b * C_ + c)) * HW;
    const float* fw = g_fused + (size_t)(b * C_ + c) * KK;
    if (tid < KK) wsm[tid] = fw[tid];

    // load 10x70 input tile with zero padding
    for (int idx = tid; idx < 10 * 70; idx += 256) {
        int r = idx / 70, cc = idx - r * 70;
        int iy = y0 - PAD + r;
        int ix = cc - PAD;
        float v = 0.f;
        if (iy >= 0 && iy < H_ && ix >= 0 && ix < W_) v = plane[iy * W_ + ix];
        tile[r][cc] = v;
    }
    __syncthreads();

    int ly = tid >> 6;                    // 0..3
    int lx = tid & 63;                    // 0..63
    float acc = 0.f;
    #pragma unroll
    for (int dy = 0; dy < K_; dy++) {
        #pragma unroll
        for (int dx = 0; dx < K_; dx++) {
            acc += tile[ly + dy][lx + dx] * wsm[dy * K_ + dx];
        }
    }
    g_tmp[((size_t)(b * C_ + c)) * HW + (y0 + ly) * W_ + lx] = acc;
}

// ---------------- 5) pointwise: out[b,o,p] = sum_c pw[o,c] * tmp[b,c,p] ----------------
// Tiled 64x64 GEMM, K=256. grid: (HW/64, C/64, B); 256 threads; 4x4 micro-tile/thread.
__global__ void pw_gemm_kernel(const float* __restrict__ pw, float* __restrict__ out) {
    __shared__ float As[16][64];          // [kk][oo]  (pw tile)
    __shared__ float Bs[16][64];          // [kk][pp]  (tmp tile)

    int b = blockIdx.z;
    int o0 = blockIdx.y * 64;
    int p0 = blockIdx.x * 64;
    int tid = threadIdx.x;
    int tx = tid & 15;                    // pixel group
    int ty = tid >> 4;                    // output-channel group

    const float* tmpb = g_tmp + (size_t)b * C_ * HW;
    float acc[4][4] = {};

    for (int k0 = 0; k0 < C_; k0 += 16) {
        // load As: 1024 elems; layout so kk varies fastest across threads
        #pragma unroll
        for (int i = 0; i < 4; i++) {
            int e = tid + i * 256;
            int kk = e & 15, oo = e >> 4;
            As[kk][oo] = pw[(o0 + oo) * C_ + k0 + kk];
        }
        // load Bs: coalesced along pixels
        #pragma unroll
        for (int i = 0; i < 4; i++) {
            int e = tid + i * 256;
            int kk = e >> 6, pp = e & 63;
            Bs[kk][pp] = tmpb[(size_t)(k0 + kk) * HW + p0 + pp];
        }
        __syncthreads();
        #pragma unroll
        for (int kk = 0; kk < 16; kk++) {
            float4 a = *(const float4*)&As[kk][ty * 4];
            float4 bb = *(const float4*)&Bs[kk][tx * 4];
            float av[4] = {a.x, a.y, a.z, a.w};
            float bv[4] = {bb.x, bb.y, bb.z, bb.w};
            #pragma unroll
            for (int i = 0; i < 4; i++)
                #pragma unroll
                for (int j = 0; j < 4; j++)
                    acc[i][j] += av[i] * bv[j];
        }
        __syncthreads();
    }

    #pragma unroll
    for (int i = 0; i < 4; i++) {
        float4 v = make_float4(acc[i][0], acc[i][1], acc[i][2], acc[i][3]);
        *(float4*)&out[((size_t)(b * C_ + o0 + ty * 4 + i)) * HW + p0 + tx * 4] = v;
    }
}

// ---------------- launch ----------------
extern "C" void kernel_launch(void* const* d_in, const int* in_sizes, int n_in,
                              void* d_out, int out_size) {
    const float* x  = (const float*)d_in[0];   // [16,256,64,64]
    const float* dw = (const float*)d_in[1];   // [256,1,7,7]
    const float* pw = (const float*)d_in[2];   // [256,256]
    const float* w1 = (const float*)d_in[3];   // [64,256]
    const float* b1 = (const float*)d_in[4];   // [64]
    const float* w2 = (const float*)d_in[5];   // [12544,64]
    const float* b2 = (const float*)d_in[6];   // [12544]
    float* out = (float*)d_out;

    pool_kernel<<<B_ * C_, 256>>>(x);
    mlp1_kernel<<<1, 1024>>>(w1, b1);
    gen_kernel<<<(B_ * CKK + 255) / 256, 256>>>(dw, w2, b2);
    dwconv_kernel<<<dim3(HW / 256, C_, B_), 256>>>(x);
    pw_gemm_kernel<<<dim3(HW / 64, C_ / 64, B_), 256>>>(pw, out);
}

// round 2
// speedup vs baseline: 2.4120x; 2.4120x over previous
#include <cuda_runtime.h>
#include <math.h>
#include <stdint.h>

#define B_  16
#define C_  256
#define H_  64
#define W_  64
#define K_  7
#define PAD 3
#define HW  (H_ * W_)          // 4096
#define KK  (K_ * K_)          // 49
#define CR  (C_ / 4)           // 64 hidden dim
#define CKK (C_ * KK)          // 12544

// ---------------- scratch (device globals; no allocs allowed) ----------------
__device__ float g_pooled[B_ * C_];          // [B, C] mean
__device__ float g_h[B_ * CR];               // [B, 64] gelu hidden
__device__ float g_fused[B_ * C_ * KK];      // [B, C, 49] fused dyn kernels
__device__ float g_tmp[B_ * C_ * HW];        // [B, C, H, W] depthwise output (67 MB)

// ---------------- cp.async helpers ----------------
__device__ __forceinline__ void cp_async16(void* smem, const void* gmem) {
    uint32_t s = (uint32_t)__cvta_generic_to_shared(smem);
    asm volatile("cp.async.ca.shared.global [%0], [%1], 16;\n" :: "r"(s), "l"(gmem));
}
#define CP_COMMIT() asm volatile("cp.async.commit_group;\n")
#define CP_WAIT1()  asm volatile("cp.async.wait_group 1;\n")

// ---------------- 1) global average pool: x -> pooled[b,c] ----------------
__global__ void pool_kernel(const float* __restrict__ x) {
    int plane = blockIdx.x;               // b*C + c
    const float* p = x + (size_t)plane * HW;
    int tid = threadIdx.x;
    float s = 0.f;
    #pragma unroll
    for (int i = 0; i < HW / 256; i++) s += p[tid + i * 256];
    __shared__ float red[256];
    red[tid] = s;
    __syncthreads();
    for (int off = 128; off >= 32; off >>= 1) {
        if (tid < off) red[tid] += red[tid + off];
        __syncthreads();
    }
    if (tid < 32) {
        float v = red[tid];
        #pragma unroll
        for (int off = 16; off > 0; off >>= 1)
            v += __shfl_down_sync(0xffffffffu, v, off);
        if (tid == 0) g_pooled[plane] = v * (1.0f / HW);
    }
}

// ---------------- 2) h = gelu(pooled @ w1.T + b1) ----------------
__global__ void mlp1_kernel(const float* __restrict__ w1, const float* __restrict__ b1) {
    int tid = threadIdx.x;                // 0..1023
    int b = tid >> 6;
    int j = tid & 63;
    const float* pr = g_pooled + b * C_;
    const float* wr = w1 + j * C_;
    float acc = b1[j];
    #pragma unroll 8
    for (int c = 0; c < C_; c++) acc += pr[c] * wr[c];
    float g = 0.5f * acc * (1.0f + erff(acc * 0.70710678118654752f));
    g_h[tid] = g;
}

// ---------------- 3) fused[b, r] = dw[r] + b2[r] + sum_j h[b,j]*w2[r,j] ----------------
// Block: 256 threads = 16 batches x 16 r-values. w2 row read once, broadcast to 16 b.
__global__ void gen_kernel(const float* __restrict__ dw, const float* __restrict__ w2,
                           const float* __restrict__ b2) {
    __shared__ float hsm[16][65];         // pad 65: conflict-free across b
    int tid = threadIdx.x;
    for (int i = tid; i < B_ * CR; i += 256) hsm[i >> 6][i & 63] = g_h[i];
    __syncthreads();

    int b  = tid & 15;
    int rl = tid >> 4;
    int r  = blockIdx.x * 16 + rl;
    const float4* wr = (const float4*)(w2 + (size_t)r * CR);
    const float* hv = hsm[b];
    float acc = b2[r] + dw[r];
    #pragma unroll
    for (int j4 = 0; j4 < CR / 4; j4++) {
        float4 w4 = wr[j4];               // broadcast across the 16 b-threads
        acc += hv[4*j4]   * w4.x + hv[4*j4+1] * w4.y
             + hv[4*j4+2] * w4.z + hv[4*j4+3] * w4.w;
    }
    g_fused[(size_t)b * CKK + r] = acc;
}

// ---------------- 4) per-sample depthwise 7x7 conv -> g_tmp ----------------
// grid (H/32, C, B); block 256 = 16 tcols x 16 trows; each thread: 2 rows x 4 cols.
__global__ void __launch_bounds__(256) dwconv_kernel(const float* __restrict__ x) {
    __shared__ float tile[38][72];        // (32+6) x (64+6), padded cols
    __shared__ float wsm[KK];

    int b = blockIdx.z, c = blockIdx.y;
    int y0 = blockIdx.x * 32;
    int tid = threadIdx.x;

    const float* plane = x + ((size_t)(b * C_ + c)) * HW;
    const float* fw = g_fused + (size_t)(b * C_ + c) * KK;
    if (tid < KK) wsm[tid] = fw[tid];

    // fill 38x70 input tile with zero halo
    for (int idx = tid; idx < 38 * 70; idx += 256) {
        int r = idx / 70, cc = idx - r * 70;
        int iy = y0 - PAD + r;
        int ix = cc - PAD;
        float v = 0.f;
        if (iy >= 0 && iy < H_ && ix >= 0 && ix < W_) v = plane[iy * W_ + ix];
        tile[r][cc] = v;
    }
    __syncthreads();

    // weights into registers
    float w[KK];
    #pragma unroll
    for (int i = 0; i < KK; i++) w[i] = wsm[i];

    int tx = tid & 15;                    // col group: cols 4*tx .. 4*tx+3
    int ty = tid >> 4;                    // row group: rows 2*ty, 2*ty+1
    int c0 = 4 * tx;
    int r0 = 2 * ty;

    float acc[2][4] = {};
    #pragma unroll
    for (int ir = 0; ir < 8; ir++) {      // relative input row
        float v[10];
        const float* trow = &tile[r0 + ir][c0];
        float4 v03 = *(const float4*)&trow[0];
        float4 v47 = *(const float4*)&trow[4];
        float2 v89 = *(const float2*)&trow[8];
        v[0]=v03.x; v[1]=v03.y; v[2]=v03.z; v[3]=v03.w;
        v[4]=v47.x; v[5]=v47.y; v[6]=v47.z; v[7]=v47.w;
        v[8]=v89.x; v[9]=v89.y;
        #pragma unroll
        for (int r = 0; r < 2; r++) {
            int dy = ir - r;
            if (dy >= 0 && dy < K_) {
                #pragma unroll
                for (int dx = 0; dx < K_; dx++) {
                    float wv = w[dy * K_ + dx];
                    #pragma unroll
                    for (int j = 0; j < 4; j++)
                        acc[r][j] += v[j + dx] * wv;
                }
            }
        }
    }

    float* outp = g_tmp + ((size_t)(b * C_ + c)) * HW;
    #pragma unroll
    for (int r = 0; r < 2; r++) {
        float4 o = make_float4(acc[r][0], acc[r][1], acc[r][2], acc[r][3]);
        *(float4*)&outp[(y0 + r0 + r) * W_ + c0] = o;
    }
}

// ---------------- 5) pointwise via tf32 tensor cores ----------------
// Per batch GEMM: Out[256,4096] = PW[256,256] x T[256,4096].
// Block tile M=128, N=128, K-chunk=16, double-buffered cp.async.
// 8 warps in 2(m) x 4(n); warp tile 64x32 = 4x4 m16n8k8 mmas.
__global__ void __launch_bounds__(256) pw_gemm_kernel(const float* __restrict__ pw,
                                                      float* __restrict__ out) {
    __shared__ float As[2][128][20];      // [buf][m][k] pad 20 -> conflict-free frags
    __shared__ float Bs[2][16][136];      // [buf][k][n] pad 136 -> conflict-free frags

    int b  = blockIdx.z;
    int o0 = blockIdx.y * 128;
    int p0 = blockIdx.x * 128;
    int tid = threadIdx.x;
    int lane = tid & 31, warp = tid >> 5;
    int wm = warp >> 2, wn = warp & 3;
    int grp = lane >> 2, tg = lane & 3;

    const float* tmpb = g_tmp + (size_t)b * C_ * HW;

    // stage loader: K-chunk kc covers k = kc*16 .. kc*16+15
    auto load_stage = [&](int buf, int kc) {
        int k0 = kc * 16;
        #pragma unroll
        for (int i = 0; i < 2; i++) {     // A: 128x16 = 512 float4
            int f = tid + i * 256;
            int m = f >> 2, k4 = f & 3;
            cp_async16(&As[buf][m][k4 * 4], pw + (size_t)(o0 + m) * C_ + k0 + k4 * 4);
        }
        #pragma unroll
        for (int i = 0; i < 2; i++) {     // B: 16x128 = 512 float4
            int f = tid + i * 256;
            int kk = f >> 5, p4 = f & 31;
            cp_async16(&Bs[buf][kk][p4 * 4], tmpb + (size_t)(k0 + kk) * HW + p0 + p4 * 4);
        }
    };

    float acc[4][4][4] = {};              // [mi][ni][reg]

    load_stage(0, 0);
    CP_COMMIT();

    for (int kc = 0; kc < 16; kc++) {
        if (kc + 1 < 16) load_stage((kc + 1) & 1, kc + 1);
        CP_COMMIT();
        CP_WAIT1();
        __syncthreads();

        int buf = kc & 1;
        #pragma unroll
        for (int ks = 0; ks < 2; ks++) {
            int kk = ks * 8;
            uint32_t a[4][4], bf[4][2];
            #pragma unroll
            for (int mi = 0; mi < 4; mi++) {
                int row = wm * 64 + mi * 16 + grp;
                a[mi][0] = __float_as_uint(As[buf][row][kk + tg]);
                a[mi][1] = __float_as_uint(As[buf][row + 8][kk + tg]);
                a[mi][2] = __float_as_uint(As[buf][row][kk + tg + 4]);
                a[mi][3] = __float_as_uint(As[buf][row + 8][kk + tg + 4]);
            }
            #pragma unroll
            for (int ni = 0; ni < 4; ni++) {
                int col = wn * 32 + ni * 8 + grp;
                bf[ni][0] = __float_as_uint(Bs[buf][kk + tg][col]);
                bf[ni][1] = __float_as_uint(Bs[buf][kk + tg + 4][col]);
            }
            #pragma unroll
            for (int mi = 0; mi < 4; mi++)
                #pragma unroll
                for (int ni = 0; ni < 4; ni++) {
                    asm volatile(
                        "mma.sync.aligned.m16n8k8.row.col.f32.tf32.tf32.f32 "
                        "{%0,%1,%2,%3}, {%4,%5,%6,%7}, {%8,%9}, {%0,%1,%2,%3};\n"
                        : "+f"(acc[mi][ni][0]), "+f"(acc[mi][ni][1]),
                          "+f"(acc[mi][ni][2]), "+f"(acc[mi][ni][3])
                        : "r"(a[mi][0]), "r"(a[mi][1]), "r"(a[mi][2]), "r"(a[mi][3]),
                          "r"(bf[ni][0]), "r"(bf[ni][1]));
                }
        }
        __syncthreads();
    }

    // epilogue: c0:(grp, 2tg) c1:(grp, 2tg+1) c2:(grp+8, 2tg) c3:(grp+8, 2tg+1)
    #pragma unroll
    for (int mi = 0; mi < 4; mi++) {
        #pragma unroll
        for (int ni = 0; ni < 4; ni++) {
            int o = o0 + wm * 64 + mi * 16 + grp;
            int p = p0 + wn * 32 + ni * 8 + tg * 2;
            float2 lo = make_float2(acc[mi][ni][0], acc[mi][ni][1]);
            float2 hi = make_float2(acc[mi][ni][2], acc[mi][ni][3]);
            *(float2*)(out + ((size_t)(b * C_ + o)) * HW + p)     = lo;
            *(float2*)(out + ((size_t)(b * C_ + o + 8)) * HW + p) = hi;
        }
    }
}

// ---------------- launch ----------------
extern "C" void kernel_launch(void* const* d_in, const int* in_sizes, int n_in,
                              void* d_out, int out_size) {
    const float* x  = (const float*)d_in[0];   // [16,256,64,64]
    const float* dw = (const float*)d_in[1];   // [256,1,7,7]
    const float* pw = (const float*)d_in[2];   // [256,256]
    const float* w1 = (const float*)d_in[3];   // [64,256]
    const float* b1 = (const float*)d_in[4];   // [64]
    const float* w2 = (const float*)d_in[5];   // [12544,64]
    const float* b2 = (const float*)d_in[6];   // [12544]
    float* out = (float*)d_out;

    pool_kernel<<<B_ * C_, 256>>>(x);
    mlp1_kernel<<<1, 1024>>>(w1, b1);
    gen_kernel<<<CKK / 16, 256>>>(dw, w2, b2);
    dwconv_kernel<<<dim3(H_ / 32, C_, B_), 256>>>(x);
    pw_gemm_kernel<<<dim3(HW / 128, C_ / 128, B_), 256>>>(pw, out);
}